// round 11
// baseline (speedup 1.0000x reference)
#include <cuda_runtime.h>
#include <cuda_fp16.h>
#include <stdint.h>

// Problem dims
#define BATCH 64
#define SEQ   512
#define DIN   256
#define HID   1024
#define NG    4096            // 4*HID
#define MTOT  32768           // BATCH*SEQ

// ---------------- scratch (device globals; no allocations allowed) ------------
__device__ __half g_X2[(size_t)MTOT * DIN];          // 16.8 MB  X in fp16
__device__ __half g_WxT[(size_t)NG * DIN];           //  2 MB    Wx^T  [n][k]
__device__ uint2  g_WhP[128][8192];                  //  8.4 MB  Wh frag-packed per block
__device__ float  g_bias[NG];
__device__ float  g_xg[(size_t)MTOT * NG];           // 537 MB   xg, layout [t][b][4H]
__device__ __half g_H2[2][BATCH * HID];              // ping-pong H (fp16)
__device__ float  g_C[BATCH * HID];                  // cell state (fp32)
__device__ float  g_Hs[(size_t)MTOT * HID];          // 134 MB   all H_t, [b*SEQ+t][h]
__device__ unsigned g_bar_count;                     // grid barrier counter

// ---------------- helpers -----------------------------------------------------
__device__ __forceinline__ void mma16816(float c[4],
    uint32_t a0, uint32_t a1, uint32_t a2, uint32_t a3,
    uint32_t b0, uint32_t b1)
{
    asm volatile(
        "mma.sync.aligned.m16n8k16.row.col.f32.f16.f16.f32 "
        "{%0,%1,%2,%3}, {%4,%5,%6,%7}, {%8,%9}, {%0,%1,%2,%3};\n"
        : "+f"(c[0]), "+f"(c[1]), "+f"(c[2]), "+f"(c[3])
        : "r"(a0), "r"(a1), "r"(a2), "r"(a3), "r"(b0), "r"(b1));
}

__device__ __forceinline__ float sigf(float x) { return 1.0f / (1.0f + __expf(-x)); }

__device__ __forceinline__ uint32_t ldcg_u32(const __half* p) {
    uint32_t v;
    asm volatile("ld.global.cg.b32 %0, [%1];" : "=r"(v) : "l"(p));
    return v;
}
__device__ __forceinline__ float2 ldcg_f2(const float* p) {
    float2 v;
    asm volatile("ld.global.cg.v2.f32 {%0,%1}, [%2];" : "=f"(v.x), "=f"(v.y) : "l"(p));
    return v;
}

// ---------------- prep kernels ------------------------------------------------
__global__ void k_init()
{
    if (threadIdx.x == 0 && blockIdx.x == 0) g_bar_count = 0u;
}

__global__ void k_convX(const float* __restrict__ X)
{
    size_t i = (size_t)blockIdx.x * blockDim.x + threadIdx.x;
    if (i < (size_t)MTOT * DIN) g_X2[i] = __float2half(X[i]);
}

__global__ void k_prepWxT(const float* __restrict__ Wxi, const float* __restrict__ Wxf,
                          const float* __restrict__ Wxo, const float* __restrict__ Wxc)
{
    int idx = blockIdx.x * blockDim.x + threadIdx.x;       // over NG*DIN
    if (idx >= NG * DIN) return;
    int n = idx >> 8;          // /256
    int k = idx & 255;
    int gate = n >> 10, h = n & 1023;
    const float* W = (gate == 0) ? Wxi : (gate == 1) ? Wxf : (gate == 2) ? Wxo : Wxc;
    g_WxT[idx] = __float2half(W[k * HID + h]);
}

// Wh frag-packed: g_WhP[blk][(kiter*4+g)*32 + lane] =
//   {Wh[k0][n],Wh[k0+1][n]} | {Wh[k0+8][n],Wh[k0+9][n]}
// with n = blk*8 + gid, k0 = kiter*16 + tig*2, lane = gid*4 + tig
__global__ void k_prepWhP(const float* __restrict__ Whi, const float* __restrict__ Whf,
                          const float* __restrict__ Who, const float* __restrict__ Whc)
{
    int idx = blockIdx.x * blockDim.x + threadIdx.x;      // over 128*8192
    if (idx >= 128 * 8192) return;
    int e    = idx & 8191;
    int blk  = idx >> 13;
    int lane = e & 31;
    int g    = (e >> 5) & 3;
    int kiter= e >> 7;
    int gid  = lane >> 2, tig = lane & 3;
    int n    = blk * 8 + gid;
    int k0   = kiter * 16 + tig * 2;
    const float* W = (g == 0) ? Whi : (g == 1) ? Whf : (g == 2) ? Who : Whc;
    __half2 lo = __floats2half2_rn(W[(size_t)k0 * HID + n],       W[(size_t)(k0 + 1) * HID + n]);
    __half2 hi = __floats2half2_rn(W[(size_t)(k0 + 8) * HID + n], W[(size_t)(k0 + 9) * HID + n]);
    uint2 v;
    v.x = *(uint32_t*)&lo;
    v.y = *(uint32_t*)&hi;
    g_WhP[blk][e] = v;
}

__global__ void k_prepBias(const float* __restrict__ bi, const float* __restrict__ bf,
                           const float* __restrict__ bo, const float* __restrict__ bc)
{
    int n = blockIdx.x * blockDim.x + threadIdx.x;
    if (n >= NG) return;
    int gate = n >> 10, h = n & 1023;
    const float* b = (gate == 0) ? bi : (gate == 1) ? bf : (gate == 2) ? bo : bc;
    g_bias[n] = b[h];
}

__global__ void k_prepState(const float* __restrict__ H0, const float* __restrict__ C0)
{
    int i = blockIdx.x * blockDim.x + threadIdx.x;
    if (i >= BATCH * HID) return;
    g_H2[0][i] = __float2half(H0[i]);
    g_C[i] = C0[i];
}

// ---------------- phase 1: xg = X @ Wx + b  (fp16 MMA, fp32 acc) --------------
__global__ void __launch_bounds__(128) k_xg()
{
    const int warp = threadIdx.x >> 5;
    const int lane = threadIdx.x & 31;
    const int gid  = lane >> 2;
    const int tig  = lane & 3;
    const int m0   = blockIdx.y * 64 + warp * 16 + gid;
    const int m1   = m0 + 8;
    const int n_base = blockIdx.x * 32;

    float c[4][4];
#pragma unroll
    for (int nc = 0; nc < 4; nc++)
#pragma unroll
        for (int r = 0; r < 4; r++) c[nc][r] = 0.0f;

#pragma unroll 4
    for (int k0 = 0; k0 < DIN; k0 += 16) {
        int ka = k0 + tig * 2;
        uint32_t a0 = *(const uint32_t*)&g_X2[(size_t)m0 * DIN + ka];
        uint32_t a1 = *(const uint32_t*)&g_X2[(size_t)m1 * DIN + ka];
        uint32_t a2 = *(const uint32_t*)&g_X2[(size_t)m0 * DIN + ka + 8];
        uint32_t a3 = *(const uint32_t*)&g_X2[(size_t)m1 * DIN + ka + 8];
#pragma unroll
        for (int nc = 0; nc < 4; nc++) {
            int n = n_base + nc * 8 + gid;
            uint32_t b0 = *(const uint32_t*)&g_WxT[(size_t)n * DIN + ka];
            uint32_t b1 = *(const uint32_t*)&g_WxT[(size_t)n * DIN + ka + 8];
            mma16816(c[nc], a0, a1, a2, a3, b0, b1);
        }
    }

    const int b0i = m0 >> 9, s0 = m0 & 511;
    const int b1i = m1 >> 9, s1 = m1 & 511;
    const size_t row0 = (size_t)s0 * BATCH + b0i;
    const size_t row1 = (size_t)s1 * BATCH + b1i;
#pragma unroll
    for (int nc = 0; nc < 4; nc++) {
        int col = n_base + nc * 8 + tig * 2;
        float bx = g_bias[col], by = g_bias[col + 1];
        float2 v0 = make_float2(c[nc][0] + bx, c[nc][1] + by);
        float2 v1 = make_float2(c[nc][2] + bx, c[nc][3] + by);
        *(float2*)&g_xg[row0 * NG + col] = v0;
        *(float2*)&g_xg[row1 * NG + col] = v1;
    }
}

// ---------------- persistent scan kernel --------------------------------------
// 128 blocks x 512 threads (no clusters!). Block owns h-slice [h0,h0+8) x 4 gates.
// Warp (kg = warp>>2, wr = warp&3): rows [wr*16, wr*16+16), k in [kg*256, +256).
// Wh frag-packed in smem (loaded once). A-fragments read DIRECTLY from L2 via
// ld.global.cg (disjoint per warp; 128KB/CTA/step, latency hidden by 4 warps/SMSP).
// 4-way split-K reduce in smem; epilogue + C-state on kg==0. Grid barrier per step.
#define RED 17           // padded partial stride (floats)

#define SWP_BYTES  (8192 * 8)                         // 65536
#define SRED_BYTES (3 * 128 * RED * 4)                // 26112
#define SCAN_SMEM_BYTES (SWP_BYTES + SRED_BYTES)      // 91648

__global__ void __launch_bounds__(512, 1) k_scan()
{
    extern __shared__ char dsm[];
    uint2* sWhP = (uint2*)dsm;                        // 64 KB packed Wh frags
    float* sRed = (float*)(dsm + SWP_BYTES);          // 26 KB partials

    const int tid  = threadIdx.x;
    const int warp = tid >> 5;
    const int lane = tid & 31;
    const int gid  = lane >> 2;
    const int tig  = lane & 3;
    const int kg   = warp >> 2;             // 0..3 : k quarter
    const int wr   = warp & 3;              // 0..3 : row group
    const int h0   = blockIdx.x * 8;
    const int r0   = wr * 16 + gid;
    const int r1   = r0 + 8;
    const int kbase = kg * 256;

    // ---- load packed Wh frags (once): 8192 uint2 = 64 KB ----
    {
        const uint2* src = g_WhP[blockIdx.x];
        for (int i = tid; i < 8192; i += 512) sWhP[i] = src[i];
    }

    // ---- C state in registers (kg==0 threads own output (b,h)) ----
    const int hc = h0 + tig * 2;
    float C00 = 0.f, C01 = 0.f, C10 = 0.f, C11 = 0.f;
    if (kg == 0) {
        C00 = g_C[r0 * HID + hc];
        C01 = g_C[r0 * HID + hc + 1];
        C10 = g_C[r1 * HID + hc];
        C11 = g_C[r1 * HID + hc + 1];
    }
    __syncthreads();

    for (int t = 0; t < SEQ; t++) {
        const __half* __restrict__ Hin  = g_H2[t & 1];
        __half* __restrict__       Hout = g_H2[(t + 1) & 1];

        // ---- accumulators: kg0 from xg, others zero ----
        float c[4][4];
        if (kg == 0) {
            const size_t xr0 = ((size_t)t * BATCH + r0) * NG;
            const size_t xr1 = ((size_t)t * BATCH + r1) * NG;
#pragma unroll
            for (int g = 0; g < 4; g++) {
                int col = g * HID + hc;
                float2 x0 = ldcg_f2(&g_xg[xr0 + col]);
                float2 x1 = ldcg_f2(&g_xg[xr1 + col]);
                c[g][0] = x0.x; c[g][1] = x0.y; c[g][2] = x1.x; c[g][3] = x1.y;
            }
        } else {
#pragma unroll
            for (int g = 0; g < 4; g++)
#pragma unroll
                for (int r = 0; r < 4; r++) c[g][r] = 0.0f;
        }

        // ---- K loop: 16 iters over this quarter; A-frags straight from L2 ----
#pragma unroll 8
        for (int it = 0; it < 16; it++) {
            int ka = kbase + it * 16 + tig * 2;
            uint32_t a0 = ldcg_u32(&Hin[r0 * HID + ka]);
            uint32_t a1 = ldcg_u32(&Hin[r1 * HID + ka]);
            uint32_t a2 = ldcg_u32(&Hin[r0 * HID + ka + 8]);
            uint32_t a3 = ldcg_u32(&Hin[r1 * HID + ka + 8]);
            const int kiter = kg * 16 + it;
#pragma unroll
            for (int g = 0; g < 4; g++) {
                uint2 b = sWhP[(kiter * 4 + g) * 32 + lane];
                mma16816(c[g], a0, a1, a2, a3, b.x, b.y);
            }
        }

        // ---- split-K reduce: kg 1..3 write partials ----
        if (kg != 0) {
            float* dst = &sRed[((kg - 1) * 128 + wr * 32 + lane) * RED];
#pragma unroll
            for (int g = 0; g < 4; g++)
#pragma unroll
                for (int r = 0; r < 4; r++) dst[g * 4 + r] = c[g][r];
        }
        __syncthreads();

        if (kg == 0) {
#pragma unroll
            for (int q = 0; q < 3; q++) {
                const float* src = &sRed[(q * 128 + wr * 32 + lane) * RED];
#pragma unroll
                for (int g = 0; g < 4; g++)
#pragma unroll
                    for (int r = 0; r < 4; r++) c[g][r] += src[g * 4 + r];
            }

            // ---- epilogue: gates, C/H update ----
#pragma unroll
            for (int p = 0; p < 2; p++) {
                int br = p ? r1 : r0;
                int ri = p * 2;
                float iv0 = sigf(c[0][ri]),  iv1 = sigf(c[0][ri + 1]);
                float fv0 = sigf(c[1][ri]),  fv1 = sigf(c[1][ri + 1]);
                float ov0 = sigf(c[2][ri]),  ov1 = sigf(c[2][ri + 1]);
                float cv0 = tanhf(c[3][ri]), cv1 = tanhf(c[3][ri + 1]);
                float Ca = p ? C10 : C00;
                float Cb = p ? C11 : C01;
                float Cn0 = fv0 * Ca + iv0 * cv0;
                float Cn1 = fv1 * Cb + iv1 * cv1;
                if (p) { C10 = Cn0; C11 = Cn1; } else { C00 = Cn0; C01 = Cn1; }
                float Hn0 = ov0 * tanhf(Cn0);
                float Hn1 = ov1 * tanhf(Cn1);
                __half2 hv = __floats2half2_rn(Hn0, Hn1);
                asm volatile("st.global.cg.b32 [%0], %1;" ::
                             "l"(&Hout[br * HID + hc]), "r"(*(uint32_t*)&hv));
                asm volatile("st.global.cg.v2.f32 [%0], {%1,%2};" ::
                             "l"(&g_Hs[((size_t)br * SEQ + t) * HID + hc]),
                             "f"(Hn0), "f"(Hn1));
            }
        }

        // ---- grid-wide barrier ----
        __threadfence();
        __syncthreads();
        if (tid == 0) {
            asm volatile("red.release.gpu.global.add.u32 [%0], 1;" :: "l"(&g_bar_count));
            unsigned target = 128u * (unsigned)(t + 1);
            unsigned v;
            do {
                asm volatile("ld.acquire.gpu.global.u32 %0, [%1];" : "=r"(v) : "l"(&g_bar_count));
            } while (v < target);
        }
        __syncthreads();
    }

    // write back C state (kg0 owns it)
    if (kg == 0) {
        g_C[r0 * HID + hc]     = C00;
        g_C[r0 * HID + hc + 1] = C01;
        g_C[r1 * HID + hc]     = C10;
        g_C[r1 * HID + hc + 1] = C11;
    }
}

// ---------------- pred = Hs @ Wd + bd ----------------------------------------
__global__ void k_pred(const float* __restrict__ Wd, const float* __restrict__ bd,
                       float* __restrict__ out, int out_size)
{
    int wg   = (blockIdx.x * blockDim.x + threadIdx.x) >> 5;   // one warp per row
    int lane = threadIdx.x & 31;
    if (wg >= MTOT) return;
    float s = 0.0f;
    const float* row = &g_Hs[(size_t)wg * HID];
#pragma unroll 8
    for (int k = lane; k < HID; k += 32) s += row[k] * Wd[k];
#pragma unroll
    for (int off = 16; off; off >>= 1) s += __shfl_down_sync(0xFFFFFFFFu, s, off);
    if (lane == 0 && wg < out_size) out[wg] = s + bd[0];
}

// ---------------- final Hf / Cf copy-out -------------------------------------
__global__ void k_final(float* __restrict__ out, int out_size)
{
    int i = blockIdx.x * blockDim.x + threadIdx.x;
    if (i >= BATCH * HID) return;
    int b = i >> 10, h = i & 1023;
    int o1 = MTOT + i;                  // Hf
    int o2 = MTOT + BATCH * HID + i;    // Cf
    if (o1 < out_size) out[o1] = g_Hs[(size_t)(b * SEQ + (SEQ - 1)) * HID + h];
    if (o2 < out_size) out[o2] = g_C[i];
}

// ---------------- launch ------------------------------------------------------
extern "C" void kernel_launch(void* const* d_in, const int* in_sizes, int n_in,
                              void* d_out, int out_size)
{
    const float* X   = (const float*)d_in[0];
    const float* H0  = (const float*)d_in[1];
    const float* C0  = (const float*)d_in[2];
    const float* Wxi = (const float*)d_in[3];
    const float* Whi = (const float*)d_in[4];
    const float* bi  = (const float*)d_in[5];
    const float* Wxf = (const float*)d_in[6];
    const float* Whf = (const float*)d_in[7];
    const float* bf  = (const float*)d_in[8];
    const float* Wxo = (const float*)d_in[9];
    const float* Who = (const float*)d_in[10];
    const float* bo  = (const float*)d_in[11];
    const float* Wxc = (const float*)d_in[12];
    const float* Whc = (const float*)d_in[13];
    const float* bc  = (const float*)d_in[14];
    const float* Wd  = (const float*)d_in[15];
    const float* bd  = (const float*)d_in[16];
    float* out = (float*)d_out;

    static int smem_set = 0;
    if (!smem_set) {
        cudaFuncSetAttribute(k_scan, cudaFuncAttributeMaxDynamicSharedMemorySize,
                             SCAN_SMEM_BYTES);
        smem_set = 1;
    }

    // prep
    k_init<<<1, 32>>>();
    k_convX<<<(MTOT * DIN + 1023) / 1024, 1024>>>(X);
    k_prepWxT<<<(NG * DIN + 255) / 256, 256>>>(Wxi, Wxf, Wxo, Wxc);
    k_prepWhP<<<(128 * 8192 + 255) / 256, 256>>>(Whi, Whf, Who, Whc);
    k_prepBias<<<(NG + 255) / 256, 256>>>(bi, bf, bo, bc);
    k_prepState<<<(BATCH * HID + 255) / 256, 256>>>(H0, C0);

    // phase 1: xg
    dim3 g1(NG / 32, MTOT / 64);
    k_xg<<<g1, 128>>>();

    // persistent scan (all 512 steps in one kernel)
    k_scan<<<128, 512, SCAN_SMEM_BYTES>>>();

    // outputs
    k_pred<<<(MTOT * 32 + 255) / 256, 256>>>(Wd, bd, out, out_size);
    k_final<<<(BATCH * HID + 255) / 256, 256>>>(out, out_size);
}

// round 14
// speedup vs baseline: 1.4886x; 1.4886x over previous
#include <cuda_runtime.h>
#include <cuda_fp16.h>
#include <stdint.h>

// Problem dims
#define BATCH 64
#define SEQ   512
#define DIN   256
#define HID   1024
#define NG    4096            // 4*HID
#define MTOT  32768           // BATCH*SEQ

// ---------------- scratch (device globals; no allocations allowed) ------------
__device__ __half g_X2[(size_t)MTOT * DIN];          // 16.8 MB  X in fp16
__device__ __half g_WxT[(size_t)NG * DIN];           //  2 MB    Wx^T  [n][k]
__device__ uint2  g_WhP[128][8192];                  //  8.4 MB  Wh frag-packed per block
__device__ float  g_bias[NG];
__device__ float  g_xg[(size_t)MTOT * NG];           // 537 MB   xg, layout [t][b][4H]
__device__ __half g_H2[2][BATCH * HID];              // ping-pong H (fp16)
__device__ float  g_C[BATCH * HID];                  // cell state (fp32)
__device__ float  g_Hs[(size_t)MTOT * HID];          // 134 MB   all H_t, [b*SEQ+t][h]
__device__ unsigned g_bar_count;                     // grid barrier counter

// ---------------- helpers -----------------------------------------------------
__device__ __forceinline__ void mma16816(float c[4],
    uint32_t a0, uint32_t a1, uint32_t a2, uint32_t a3,
    uint32_t b0, uint32_t b1)
{
    asm volatile(
        "mma.sync.aligned.m16n8k16.row.col.f32.f16.f16.f32 "
        "{%0,%1,%2,%3}, {%4,%5,%6,%7}, {%8,%9}, {%0,%1,%2,%3};\n"
        : "+f"(c[0]), "+f"(c[1]), "+f"(c[2]), "+f"(c[3])
        : "r"(a0), "r"(a1), "r"(a2), "r"(a3), "r"(b0), "r"(b1));
}

__device__ __forceinline__ float sigf(float x) { return 1.0f / (1.0f + __expf(-x)); }

__device__ __forceinline__ float2 ldcg_f2(const float* p) {
    float2 v;
    asm volatile("ld.global.cg.v2.f32 {%0,%1}, [%2];" : "=f"(v.x), "=f"(v.y) : "l"(p));
    return v;
}

__device__ __forceinline__ uint32_t smem_u32(const void* p) {
    uint32_t a;
    asm("{ .reg .u64 t; cvta.to.shared.u64 t, %1; cvt.u32.u64 %0, t; }" : "=r"(a) : "l"(p));
    return a;
}

// ---------------- prep kernels ------------------------------------------------
__global__ void k_init()
{
    if (threadIdx.x == 0 && blockIdx.x == 0) g_bar_count = 0u;
}

__global__ void k_convX(const float* __restrict__ X)
{
    size_t i = (size_t)blockIdx.x * blockDim.x + threadIdx.x;
    if (i < (size_t)MTOT * DIN) g_X2[i] = __float2half(X[i]);
}

__global__ void k_prepWxT(const float* __restrict__ Wxi, const float* __restrict__ Wxf,
                          const float* __restrict__ Wxo, const float* __restrict__ Wxc)
{
    int idx = blockIdx.x * blockDim.x + threadIdx.x;       // over NG*DIN
    if (idx >= NG * DIN) return;
    int n = idx >> 8;          // /256
    int k = idx & 255;
    int gate = n >> 10, h = n & 1023;
    const float* W = (gate == 0) ? Wxi : (gate == 1) ? Wxf : (gate == 2) ? Wxo : Wxc;
    g_WxT[idx] = __float2half(W[k * HID + h]);
}

// Wh frag-packed: g_WhP[blk][(kiter*4+g)*32 + lane] =
//   {Wh[k0][n],Wh[k0+1][n]} | {Wh[k0+8][n],Wh[k0+9][n]}
// with n = blk*8 + gid, k0 = kiter*16 + tig*2, lane = gid*4 + tig
__global__ void k_prepWhP(const float* __restrict__ Whi, const float* __restrict__ Whf,
                          const float* __restrict__ Who, const float* __restrict__ Whc)
{
    int idx = blockIdx.x * blockDim.x + threadIdx.x;      // over 128*8192
    if (idx >= 128 * 8192) return;
    int e    = idx & 8191;
    int blk  = idx >> 13;
    int lane = e & 31;
    int g    = (e >> 5) & 3;
    int kiter= e >> 7;
    int gid  = lane >> 2, tig = lane & 3;
    int n    = blk * 8 + gid;
    int k0   = kiter * 16 + tig * 2;
    const float* W = (g == 0) ? Whi : (g == 1) ? Whf : (g == 2) ? Who : Whc;
    __half2 lo = __floats2half2_rn(W[(size_t)k0 * HID + n],       W[(size_t)(k0 + 1) * HID + n]);
    __half2 hi = __floats2half2_rn(W[(size_t)(k0 + 8) * HID + n], W[(size_t)(k0 + 9) * HID + n]);
    uint2 v;
    v.x = *(uint32_t*)&lo;
    v.y = *(uint32_t*)&hi;
    g_WhP[blk][e] = v;
}

__global__ void k_prepBias(const float* __restrict__ bi, const float* __restrict__ bf,
                           const float* __restrict__ bo, const float* __restrict__ bc)
{
    int n = blockIdx.x * blockDim.x + threadIdx.x;
    if (n >= NG) return;
    int gate = n >> 10, h = n & 1023;
    const float* b = (gate == 0) ? bi : (gate == 1) ? bf : (gate == 2) ? bo : bc;
    g_bias[n] = b[h];
}

__global__ void k_prepState(const float* __restrict__ H0, const float* __restrict__ C0)
{
    int i = blockIdx.x * blockDim.x + threadIdx.x;
    if (i >= BATCH * HID) return;
    g_H2[0][i] = __float2half(H0[i]);
    g_C[i] = C0[i];
}

// ---------------- phase 1: xg = X @ Wx + b  (fp16 MMA, fp32 acc) --------------
__global__ void __launch_bounds__(128) k_xg()
{
    const int warp = threadIdx.x >> 5;
    const int lane = threadIdx.x & 31;
    const int gid  = lane >> 2;
    const int tig  = lane & 3;
    const int m0   = blockIdx.y * 64 + warp * 16 + gid;
    const int m1   = m0 + 8;
    const int n_base = blockIdx.x * 32;

    float c[4][4];
#pragma unroll
    for (int nc = 0; nc < 4; nc++)
#pragma unroll
        for (int r = 0; r < 4; r++) c[nc][r] = 0.0f;

#pragma unroll 4
    for (int k0 = 0; k0 < DIN; k0 += 16) {
        int ka = k0 + tig * 2;
        uint32_t a0 = *(const uint32_t*)&g_X2[(size_t)m0 * DIN + ka];
        uint32_t a1 = *(const uint32_t*)&g_X2[(size_t)m1 * DIN + ka];
        uint32_t a2 = *(const uint32_t*)&g_X2[(size_t)m0 * DIN + ka + 8];
        uint32_t a3 = *(const uint32_t*)&g_X2[(size_t)m1 * DIN + ka + 8];
#pragma unroll
        for (int nc = 0; nc < 4; nc++) {
            int n = n_base + nc * 8 + gid;
            uint32_t b0 = *(const uint32_t*)&g_WxT[(size_t)n * DIN + ka];
            uint32_t b1 = *(const uint32_t*)&g_WxT[(size_t)n * DIN + ka + 8];
            mma16816(c[nc], a0, a1, a2, a3, b0, b1);
        }
    }

    const int b0i = m0 >> 9, s0 = m0 & 511;
    const int b1i = m1 >> 9, s1 = m1 & 511;
    const size_t row0 = (size_t)s0 * BATCH + b0i;
    const size_t row1 = (size_t)s1 * BATCH + b1i;
#pragma unroll
    for (int nc = 0; nc < 4; nc++) {
        int col = n_base + nc * 8 + tig * 2;
        float bx = g_bias[col], by = g_bias[col + 1];
        float2 v0 = make_float2(c[nc][0] + bx, c[nc][1] + by);
        float2 v1 = make_float2(c[nc][2] + bx, c[nc][3] + by);
        *(float2*)&g_xg[row0 * NG + col] = v0;
        *(float2*)&g_xg[row1 * NG + col] = v1;
    }
}

// ---------------- persistent scan kernel --------------------------------------
// 128 blocks x 512 threads (no clusters). Block owns h-slice [h0,h0+8) x 4 gates.
// Warp (kg = warp>>2, wr = warp&3): rows [wr*16, +16), k in [kg*256, +256).
// Wh frag-packed in smem (loaded once, 64KB). H staged per step via TMA bulk
// copies into smem in FOUR 16-row chunks, each with its own mbarrier; warp
// (kg,wr) waits only on chunk wr (stage/compute overlap). 4-way split-K reduce
// in smem (aliases sH after K-loop); epilogue + C-state on kg==0. Grid barrier.
#define SH_STRIDE 1032   // padded H row stride (halfs): conflict-free A loads
#define RED 17           // padded partial stride (floats)

#define SWP_BYTES  (8192 * 8)                         // 65536
#define SH_BYTES   (BATCH * SH_STRIDE * 2)            // 132096
#define SCAN_SMEM_BYTES (SWP_BYTES + SH_BYTES)        // 197632
#define CHUNK_BYTES (16 * HID * 2)                    // 32768 tx per chunk

__global__ void __launch_bounds__(512, 1) k_scan()
{
    extern __shared__ char dsm[];
    uint2*  sWhP = (uint2*)dsm;                       // 64 KB packed Wh frags
    __half* sH   = (__half*)(dsm + SWP_BYTES);        // [64][SH_STRIDE]
    float*  sRed = (float*)sH;                        // aliased post-K-loop
    __shared__ __align__(8) uint64_t mbar[4];

    const int tid  = threadIdx.x;
    const int warp = tid >> 5;
    const int lane = tid & 31;
    const int gid  = lane >> 2;
    const int tig  = lane & 3;
    const int kg   = warp >> 2;             // 0..3 : k quarter
    const int wr   = warp & 3;              // 0..3 : row group
    const int h0   = blockIdx.x * 8;
    const int r0   = wr * 16 + gid;
    const int r1   = r0 + 8;
    const int kbase = kg * 256;

    const uint32_t mbar_a = smem_u32(&mbar[wr]);
    const uint32_t sH_a   = smem_u32(sH);

    if (tid < 4) {
        asm volatile("mbarrier.init.shared.b64 [%0], 1;" :: "r"(smem_u32(&mbar[tid])));
    }

    // ---- load packed Wh frags (once): 8192 uint2 = 64 KB ----
    {
        const uint2* src = g_WhP[blockIdx.x];
        for (int i = tid; i < 8192; i += 512) sWhP[i] = src[i];
    }

    // ---- C state in registers (kg==0 threads own output (b,h)) ----
    const int hc = h0 + tig * 2;
    float C00 = 0.f, C01 = 0.f, C10 = 0.f, C11 = 0.f;
    if (kg == 0) {
        C00 = g_C[r0 * HID + hc];
        C01 = g_C[r0 * HID + hc + 1];
        C10 = g_C[r1 * HID + hc];
        C11 = g_C[r1 * HID + hc + 1];
    }
    __syncthreads();

    for (int t = 0; t < SEQ; t++) {
        const __half* __restrict__ Hin  = g_H2[t & 1];
        __half* __restrict__       Hout = g_H2[(t + 1) & 1];

        // ---- stage H in 4 chunks of 16 rows (32KB each); 1 issuing thread ----
        if (tid == 0) {
            asm volatile("fence.proxy.async.shared::cta;" ::: "memory");
#pragma unroll
            for (int cc = 0; cc < 4; cc++) {
                uint32_t mb = smem_u32(&mbar[cc]);
                asm volatile("mbarrier.arrive.expect_tx.shared.b64 _, [%0], %1;"
                             :: "r"(mb), "r"((uint32_t)CHUNK_BYTES));
#pragma unroll
                for (int rr = 0; rr < 16; rr++) {
                    int row = cc * 16 + rr;
                    asm volatile(
                        "cp.async.bulk.shared::cta.global.mbarrier::complete_tx::bytes "
                        "[%0], [%1], %2, [%3];"
                        :: "r"(sH_a + (uint32_t)(row * SH_STRIDE * 2)),
                           "l"(&Hin[row * HID]),
                           "r"((uint32_t)(HID * 2)),
                           "r"(mb)
                        : "memory");
                }
            }
        }

        // ---- accumulators: kg0 from xg, others zero ----
        float c[4][4];
        if (kg == 0) {
            const size_t xr0 = ((size_t)t * BATCH + r0) * NG;
            const size_t xr1 = ((size_t)t * BATCH + r1) * NG;
#pragma unroll
            for (int g = 0; g < 4; g++) {
                int col = g * HID + hc;
                float2 x0 = ldcg_f2(&g_xg[xr0 + col]);
                float2 x1 = ldcg_f2(&g_xg[xr1 + col]);
                c[g][0] = x0.x; c[g][1] = x0.y; c[g][2] = x1.x; c[g][3] = x1.y;
            }
        } else {
#pragma unroll
            for (int g = 0; g < 4; g++)
#pragma unroll
                for (int r = 0; r < 4; r++) c[g][r] = 0.0f;
        }

        // ---- wait for THIS warp's row chunk only ----
        {
            const uint32_t parity = (uint32_t)(t & 1);
            uint32_t done;
            asm volatile(
                "{\n\t.reg .pred p;\n\t"
                "mbarrier.try_wait.parity.acquire.cta.shared::cta.b64 p, [%1], %2;\n\t"
                "selp.b32 %0, 1, 0, p;\n\t}"
                : "=r"(done) : "r"(mbar_a), "r"(parity) : "memory");
            if (!done) {
                asm volatile(
                    "{\n\t.reg .pred P1;\n\t"
                    "W_%=:\n\t"
                    "mbarrier.try_wait.parity.acquire.cta.shared::cta.b64 P1, [%0], %1, 0x989680;\n\t"
                    "@P1 bra.uni D_%=;\n\t"
                    "bra.uni W_%=;\n\t"
                    "D_%=:\n\t}"
                    :: "r"(mbar_a), "r"(parity) : "memory");
            }
        }

        // ---- K loop: 16 iters over this quarter; A from smem, B packed LDS.64 ----
#pragma unroll 8
        for (int it = 0; it < 16; it++) {
            int ka = kbase + it * 16 + tig * 2;
            uint32_t a0 = *(const uint32_t*)&sH[r0 * SH_STRIDE + ka];
            uint32_t a1 = *(const uint32_t*)&sH[r1 * SH_STRIDE + ka];
            uint32_t a2 = *(const uint32_t*)&sH[r0 * SH_STRIDE + ka + 8];
            uint32_t a3 = *(const uint32_t*)&sH[r1 * SH_STRIDE + ka + 8];
            const int kiter = kg * 16 + it;
#pragma unroll
            for (int g = 0; g < 4; g++) {
                uint2 b = sWhP[(kiter * 4 + g) * 32 + lane];
                mma16816(c[g], a0, a1, a2, a3, b.x, b.y);
            }
        }

        __syncthreads();   // all sH reads done; sRed may alias

        // ---- split-K reduce: kg 1..3 write partials ----
        if (kg != 0) {
            float* dst = &sRed[((kg - 1) * 128 + wr * 32 + lane) * RED];
#pragma unroll
            for (int g = 0; g < 4; g++)
#pragma unroll
                for (int r = 0; r < 4; r++) dst[g * 4 + r] = c[g][r];
        }
        __syncthreads();

        if (kg == 0) {
#pragma unroll
            for (int q = 0; q < 3; q++) {
                const float* src = &sRed[(q * 128 + wr * 32 + lane) * RED];
#pragma unroll
                for (int g = 0; g < 4; g++)
#pragma unroll
                    for (int r = 0; r < 4; r++) c[g][r] += src[g * 4 + r];
            }

            // ---- epilogue: gates, C/H update ----
#pragma unroll
            for (int p = 0; p < 2; p++) {
                int br = p ? r1 : r0;
                int ri = p * 2;
                float iv0 = sigf(c[0][ri]),  iv1 = sigf(c[0][ri + 1]);
                float fv0 = sigf(c[1][ri]),  fv1 = sigf(c[1][ri + 1]);
                float ov0 = sigf(c[2][ri]),  ov1 = sigf(c[2][ri + 1]);
                float cv0 = tanhf(c[3][ri]), cv1 = tanhf(c[3][ri + 1]);
                float Ca = p ? C10 : C00;
                float Cb = p ? C11 : C01;
                float Cn0 = fv0 * Ca + iv0 * cv0;
                float Cn1 = fv1 * Cb + iv1 * cv1;
                if (p) { C10 = Cn0; C11 = Cn1; } else { C00 = Cn0; C01 = Cn1; }
                float Hn0 = ov0 * tanhf(Cn0);
                float Hn1 = ov1 * tanhf(Cn1);
                __half2 hv = __floats2half2_rn(Hn0, Hn1);
                asm volatile("st.global.cg.b32 [%0], %1;" ::
                             "l"(&Hout[br * HID + hc]), "r"(*(uint32_t*)&hv));
                asm volatile("st.global.cg.v2.f32 [%0], {%1,%2};" ::
                             "l"(&g_Hs[((size_t)br * SEQ + t) * HID + hc]),
                             "f"(Hn0), "f"(Hn1));
            }
        }

        // ---- grid-wide barrier (syncthreads + release-add / acquire-spin) ----
        __syncthreads();
        if (tid == 0) {
            asm volatile("red.release.gpu.global.add.u32 [%0], 1;" :: "l"(&g_bar_count));
            unsigned target = 128u * (unsigned)(t + 1);
            unsigned v;
            do {
                asm volatile("ld.acquire.gpu.global.u32 %0, [%1];" : "=r"(v) : "l"(&g_bar_count));
            } while (v < target);
        }
        __syncthreads();
    }

    // write back C state (kg0 owns it)
    if (kg == 0) {
        g_C[r0 * HID + hc]     = C00;
        g_C[r0 * HID + hc + 1] = C01;
        g_C[r1 * HID + hc]     = C10;
        g_C[r1 * HID + hc + 1] = C11;
    }
}

// ---------------- pred = Hs @ Wd + bd ----------------------------------------
__global__ void k_pred(const float* __restrict__ Wd, const float* __restrict__ bd,
                       float* __restrict__ out, int out_size)
{
    int wg   = (blockIdx.x * blockDim.x + threadIdx.x) >> 5;   // one warp per row
    int lane = threadIdx.x & 31;
    if (wg >= MTOT) return;
    float s = 0.0f;
    const float* row = &g_Hs[(size_t)wg * HID];
#pragma unroll 8
    for (int k = lane; k < HID; k += 32) s += row[k] * Wd[k];
#pragma unroll
    for (int off = 16; off; off >>= 1) s += __shfl_down_sync(0xFFFFFFFFu, s, off);
    if (lane == 0 && wg < out_size) out[wg] = s + bd[0];
}

// ---------------- final Hf / Cf copy-out -------------------------------------
__global__ void k_final(float* __restrict__ out, int out_size)
{
    int i = blockIdx.x * blockDim.x + threadIdx.x;
    if (i >= BATCH * HID) return;
    int b = i >> 10, h = i & 1023;
    int o1 = MTOT + i;                  // Hf
    int o2 = MTOT + BATCH * HID + i;    // Cf
    if (o1 < out_size) out[o1] = g_Hs[(size_t)(b * SEQ + (SEQ - 1)) * HID + h];
    if (o2 < out_size) out[o2] = g_C[i];
}

// ---------------- launch ------------------------------------------------------
extern "C" void kernel_launch(void* const* d_in, const int* in_sizes, int n_in,
                              void* d_out, int out_size)
{
    const float* X   = (const float*)d_in[0];
    const float* H0  = (const float*)d_in[1];
    const float* C0  = (const float*)d_in[2];
    const float* Wxi = (const float*)d_in[3];
    const float* Whi = (const float*)d_in[4];
    const float* bi  = (const float*)d_in[5];
    const float* Wxf = (const float*)d_in[6];
    const float* Whf = (const float*)d_in[7];
    const float* bf  = (const float*)d_in[8];
    const float* Wxo = (const float*)d_in[9];
    const float* Who = (const float*)d_in[10];
    const float* bo  = (const float*)d_in[11];
    const float* Wxc = (const float*)d_in[12];
    const float* Whc = (const float*)d_in[13];
    const float* bc  = (const float*)d_in[14];
    const float* Wd  = (const float*)d_in[15];
    const float* bd  = (const float*)d_in[16];
    float* out = (float*)d_out;

    static int smem_set = 0;
    if (!smem_set) {
        cudaFuncSetAttribute(k_scan, cudaFuncAttributeMaxDynamicSharedMemorySize,
                             SCAN_SMEM_BYTES);
        smem_set = 1;
    }

    // prep
    k_init<<<1, 32>>>();
    k_convX<<<(MTOT * DIN + 1023) / 1024, 1024>>>(X);
    k_prepWxT<<<(NG * DIN + 255) / 256, 256>>>(Wxi, Wxf, Wxo, Wxc);
    k_prepWhP<<<(128 * 8192 + 255) / 256, 256>>>(Whi, Whf, Who, Whc);
    k_prepBias<<<(NG + 255) / 256, 256>>>(bi, bf, bo, bc);
    k_prepState<<<(BATCH * HID + 255) / 256, 256>>>(H0, C0);

    // phase 1: xg
    dim3 g1(NG / 32, MTOT / 64);
    k_xg<<<g1, 128>>>();

    // persistent scan (all 512 steps in one kernel)
    k_scan<<<128, 512, SCAN_SMEM_BYTES>>>();

    // outputs
    k_pred<<<(MTOT * 32 + 255) / 256, 256>>>(Wd, bd, out, out_size);
    k_final<<<(BATCH * HID + 255) / 256, 256>>>(out, out_size);
}